// round 14
// baseline (speedup 1.0000x reference)
#include <cuda_runtime.h>
#include <math_constants.h>

#define BN    8
#define BC    256
#define BNF   16
#define BWH   784            // 28*28
#define CSTR4 3136           // float4 stride between channels of l
#define NV4   196            // float4 per wh-row
#define NTILE (BN*BNF)       // 128
#define NCHUNK 8             // wh-chunks per tile (K1)
#define K1THR 256
#define K2THR 256
#define K2CH  4              // channel-chunks per tile (K2): 64 channels each
#define CPW2  8              // channels per warp in K2

// ---------------- K1: c[n,f,wh] = sum_c (l+g)·w over a wh-chunk (R9, proven) ----
__global__ __launch_bounds__(K1THR)
void mfla_c_kernel(const float* __restrict__ l,
                   const float* __restrict__ g,
                   const float* __restrict__ w,
                   float* __restrict__ outc)
{
    __shared__ float sw[BC];
    __shared__ __align__(16) float4 part[8][28];
    __shared__ float red[8];
    __shared__ float s_gdot;

    const int tid  = threadIdx.x;
    const int tile = blockIdx.x >> 3;      // n*16 + f
    const int j    = blockIdx.x & 7;
    const int n    = tile >> 4;
    const int f    = tile & 15;

    int start4, len4;
    if ((f & 1) == 0) { start4 = (j < 7) ? 24 * j : 168;     len4 = (j < 7) ? 24 : 28; }
    else              { start4 = (j == 0) ? 0 : 24 * j + 4;  len4 = (j == 0) ? 28 : 24; }

    const float4* lb4 = reinterpret_cast<const float4*>(
        l + ((size_t)n * BC * BNF + f) * BWH);

    float wv = w[tid];
    sw[tid] = wv;
    float p = g[n * BC + tid] * wv;
    #pragma unroll
    for (int o = 16; o; o >>= 1) p += __shfl_xor_sync(0xffffffffu, p, o);
    if ((tid & 31) == 0) red[tid >> 5] = p;
    __syncthreads();
    if (tid < 8) {
        float v = red[tid];
        #pragma unroll
        for (int o = 4; o; o >>= 1) v += __shfl_xor_sync(0xffu, v, o);
        if (tid == 0) s_gdot = v;
    }

    {
        const int gq = tid >> 5;           // channel group 0..7
        const int s  = tid & 31;
        if (s < len4) {
            const float4* lp = lb4 + (size_t)(gq * 32) * CSTR4 + start4 + s;
            float4 a = make_float4(0.f, 0.f, 0.f, 0.f);
            #pragma unroll
            for (int c = 0; c < 32; ++c) {
                float4 v = lp[(size_t)c * CSTR4];
                float  ww = sw[gq * 32 + c];
                a.x = fmaf(v.x, ww, a.x);
                a.y = fmaf(v.y, ww, a.y);
                a.z = fmaf(v.z, ww, a.z);
                a.w = fmaf(v.w, ww, a.w);
            }
            part[gq][s] = a;
        }
    }
    __syncthreads();

    if (tid < len4) {
        const float gd = s_gdot;
        float4 v = make_float4(gd, gd, gd, gd);
        #pragma unroll
        for (int k = 0; k < 8; ++k) {
            float4 q = part[k][tid];
            v.x += q.x; v.y += q.y; v.z += q.z; v.w += q.w;
        }
        reinterpret_cast<float4*>(outc)[(size_t)tile * NV4 + start4 + tid] = v;
    }
}

// ---------------- K2: softmax + pool; 8 warps x 8 channels (wide MLP) ----------------
__global__ __launch_bounds__(K2THR)
void mfla_pool_kernel(const float* __restrict__ l,
                      const float* __restrict__ outc,
                      float* __restrict__ outg)
{
    __shared__ __align__(16) float sc[BWH];   // exp values
    __shared__ float red[8];
    __shared__ float s_inv;

    const int tid  = threadIdx.x;
    const int tile = blockIdx.x >> 2;      // n*16 + f
    const int cc   = blockIdx.x & 3;       // channels [64cc, 64cc+64)
    const int n    = tile >> 4;
    const int f    = tile & 15;

    // exp + partial sum
    float se = 0.f;
    if (tid < NV4) {
        float4 c4 = reinterpret_cast<const float4*>(outc + (size_t)tile * BWH)[tid];
        float4 e4 = make_float4(__expf(c4.x), __expf(c4.y), __expf(c4.z), __expf(c4.w));
        reinterpret_cast<float4*>(sc)[tid] = e4;
        se = (e4.x + e4.y) + (e4.z + e4.w);
    }
    #pragma unroll
    for (int o = 16; o; o >>= 1) se += __shfl_xor_sync(0xffffffffu, se, o);
    if ((tid & 31) == 0) red[tid >> 5] = se;
    __syncthreads();
    if (tid < 8) {
        float v = red[tid];
        #pragma unroll
        for (int o = 4; o; o >>= 1) v += __shfl_xor_sync(0xffu, v, o);
        if (tid == 0) s_inv = 1.0f / v;
    }
    __syncthreads();

    // pool: 8 warps x 8 channels each = 64 channels per CTA
    {
        const int warp = tid >> 5;
        const int lane = tid & 31;
        const int c0   = 64 * cc + CPW2 * warp;
        const float inv = s_inv;
        const float4* av = reinterpret_cast<const float4*>(sc);
        const float4* lv = reinterpret_cast<const float4*>(
            l + ((size_t)(n * BC + c0) * BNF + f) * BWH);
        float acc[CPW2] = {0.f, 0.f, 0.f, 0.f, 0.f, 0.f, 0.f, 0.f};
        for (int i = lane; i < NV4; i += 32) {
            float4 a4 = av[i];
            #pragma unroll
            for (int k = 0; k < CPW2; ++k) {
                float4 l4 = lv[(size_t)k * CSTR4 + i];
                acc[k] += a4.x * l4.x + a4.y * l4.y + a4.z * l4.z + a4.w * l4.w;
            }
        }
        #pragma unroll
        for (int k = 0; k < CPW2; ++k) {
            float a = acc[k];
            #pragma unroll
            for (int o = 16; o; o >>= 1) a += __shfl_xor_sync(0xffffffffu, a, o);
            if (lane == 0)
                outg[((size_t)n * BC + c0 + k) * BNF + f] = a * inv;
        }
    }
}

extern "C" void kernel_launch(void* const* d_in, const int* in_sizes, int n_in,
                              void* d_out, int out_size)
{
    const float* l = (const float*)d_in[0];
    const float* g = (const float*)d_in[1];
    const float* w = (const float*)d_in[2];
    float* out  = (float*)d_out;
    float* outc = out;                              // 8*16*28*28 = 100352 floats
    float* outg = out + (size_t)BN * BNF * BWH;     // 8*256*16   = 32768 floats

    mfla_c_kernel   <<<NTILE * NCHUNK, K1THR>>>(l, g, w, outc);
    mfla_pool_kernel<<<NTILE * K2CH,  K2THR>>>(l, outc, outg);
}